// round 17
// baseline (speedup 1.0000x reference)
#include <cuda_runtime.h>
#include <cuda_bf16.h>
#include <cstdint>

typedef unsigned long long ull;

#define EPSV 1e-5f

// ---------------- device scratch (no allocations allowed) ----------------
__device__ float g_h[8*64*64*128];      // BN-ReLU output NHWC [b][y][x][c]
__device__ float g_off[8*64*64*18];     // offsets [b][y][x][18]
__device__ float g_woffB[3*32*384];     // w_off repack [ky][oc(pad32)][kx*128+c], tf32
__device__ float g_wtf[9*16384];        // w_dconv per-tap [k][o*128+cperm], tf32, cols permuted [0,4,1,5,2,6,3,7]

// ---------------- tf32 helpers (baseline PTX, no sm_103a features) ----------------
__device__ __forceinline__ float cvt_tf32(float x){
    uint32_t r; asm("cvt.rna.tf32.f32 %0, %1;" : "=r"(r) : "f"(x));
    return __uint_as_float(r);
}
__device__ __forceinline__ void mma_tf32(float& c0, float& c1, float& c2, float& c3,
                                         uint32_t a0, uint32_t a1, uint32_t a2, uint32_t a3,
                                         uint32_t b0, uint32_t b1){
    asm volatile("mma.sync.aligned.m16n8k8.row.col.f32.tf32.tf32.f32 "
        "{%0,%1,%2,%3}, {%4,%5,%6,%7}, {%8,%9}, {%0,%1,%2,%3};"
        : "+f"(c0), "+f"(c1), "+f"(c2), "+f"(c3)
        : "r"(a0), "r"(a1), "r"(a2), "r"(a3), "r"(b0), "r"(b1));
}
__device__ __forceinline__ void cp_async16(uint32_t dst, const void* src){
    asm volatile("cp.async.cg.shared.global [%0], [%1], 16;" :: "r"(dst), "l"(src));
}
#define CP_ASYNC_COMMIT() asm volatile("cp.async.commit_group;" ::: "memory")
#define CP_ASYNC_WAIT0()  asm volatile("cp.async.wait_group 0;" ::: "memory")

// ---------------- kernel 0: weight repack (tf32) ----------------
__global__ void k_prep(const float* __restrict__ woff, const float* __restrict__ wdc)
{
    int i = blockIdx.x*256 + threadIdx.x;
    if (i < 3*32*384) {
        int ky = i / 12288;
        int r  = i - ky*12288;
        int oc = r / 384;
        int kc = r - oc*384;
        int kx = kc >> 7, c = kc & 127;
        g_woffB[i] = (oc < 18) ? cvt_tf32(woff[(oc*128 + c)*9 + ky*3 + kx]) : 0.f;
    }
    if (i < 9*128*128) {
        int k = i / 16384;
        int r = i - k*16384;        // r = o*128 + cpos
        int o = r >> 7, cpos = r & 127;
        int g = cpos >> 3, p = cpos & 7;
        int w = (p >> 1) + (p & 1)*4;   // inverse of perm [0,4,1,5,2,6,3,7]
        g_wtf[i] = cvt_tf32(wdc[(size_t)(o*128 + g*8 + w)*9 + k]);
    }
}

// ---------------- kernel 1: BN + ReLU, NCHW -> NHWC ----------------
__global__ __launch_bounds__(256) void k_bnrelu(const float* __restrict__ x,
    const float* __restrict__ gam, const float* __restrict__ bet,
    const float* __restrict__ mea, const float* __restrict__ var)
{
    __shared__ float s[128*65];
    const int t = threadIdx.x;
    const int b = blockIdx.x, y = blockIdx.y;
    #pragma unroll
    for (int i0 = 0; i0 < 8192; i0 += 256) {
        int i = i0 + t;
        int c = i >> 6, xx = i & 63;
        float val = x[(((size_t)b*128 + c)*64 + y)*64 + xx];
        float inv = __ldg(gam + c) * rsqrtf(__ldg(var + c) + EPSV);
        s[c*65 + xx] = fmaxf((val - __ldg(mea + c)) * inv + __ldg(bet + c), 0.f);
    }
    __syncthreads();
    float* hrow = g_h + ((size_t)b*64 + y)*64*128;
    #pragma unroll
    for (int i0 = 0; i0 < 8192; i0 += 256) {
        int i = i0 + t;
        int xx = i >> 7, c = i & 127;
        hrow[xx*128 + c] = s[c*65 + xx];
    }
}

// ---------------- kernel 2: offset conv via mma.sync tf32 ----------------
// grid (8,64): one (b,row) per CTA, 256 thr = 8 warps, 2 CTAs/SM.
#define SMO_TOTAL ((66*132 + 32*388)*4)
__global__ __launch_bounds__(256, 2) void k_off_mma(const float* __restrict__ boff)
{
    extern __shared__ float smo[];
    float* vrow = smo;          // 66*132
    float* Bs   = smo + 8712;   // 32*388
    const int t = threadIdx.x, warp = t >> 5, lane = t & 31;
    const int r = lane >> 2, tig = lane & 3;
    const int b = blockIdx.x, y = blockIdx.y;
    const int mbase = (warp & 3) * 16;
    const int nbase = (warp >> 2) * 16;

    float acc[2][4];
    #pragma unroll
    for (int nt = 0; nt < 2; ++nt)
        #pragma unroll
        for (int q = 0; q < 4; ++q) acc[nt][q] = 0.f;

    for (int ky = 0; ky < 3; ++ky) {
        __syncthreads();
        const int yy = y + ky - 1;
        const bool rowok = (unsigned)yy < 64u;
        const float* srcrow = g_h + ((size_t)b*64 + yy)*64*128;
        for (int i4 = t; i4 < 2112; i4 += 256) {
            int slot = i4 >> 5, c = (i4 & 31) * 4;
            int xx = slot - 1;
            float4 v = make_float4(0.f,0.f,0.f,0.f);
            if (rowok && (unsigned)xx < 64u) {
                v = *(const float4*)(srcrow + xx*128 + c);
                v.x = cvt_tf32(v.x); v.y = cvt_tf32(v.y);
                v.z = cvt_tf32(v.z); v.w = cvt_tf32(v.w);
            }
            *(float4*)(vrow + slot*132 + c) = v;
        }
        for (int i4 = t; i4 < 3072; i4 += 256) {
            int oc = i4 / 96, rem = i4 - oc*96;
            *(float4*)(Bs + oc*388 + rem*4) =
                ((const float4*)(g_woffB + ky*12288 + oc*384))[rem];
        }
        __syncthreads();
        #pragma unroll
        for (int kx = 0; kx < 3; ++kx) {
            #pragma unroll 4
            for (int s = 0; s < 16; ++s) {
                const float* ap = vrow + (mbase + r + kx)*132 + s*8 + tig;
                uint32_t a0 = __float_as_uint(ap[0]);
                uint32_t a1 = __float_as_uint(ap[8*132]);
                uint32_t a2 = __float_as_uint(ap[4]);
                uint32_t a3 = __float_as_uint(ap[8*132 + 4]);
                #pragma unroll
                for (int nt = 0; nt < 2; ++nt) {
                    const float* bp = Bs + (nbase + nt*8 + r)*388 + kx*128 + s*8 + tig;
                    mma_tf32(acc[nt][0], acc[nt][1], acc[nt][2], acc[nt][3],
                             a0, a1, a2, a3,
                             __float_as_uint(bp[0]), __float_as_uint(bp[4]));
                }
            }
        }
    }
    float* orow = g_off + ((size_t)b*64 + y)*64*18;
    const int px0 = mbase + r;
    #pragma unroll
    for (int nt = 0; nt < 2; ++nt) {
        const int oc0 = nbase + nt*8 + 2*tig;
        if (oc0 < 18) {
            float bias = __ldg(boff + oc0);
            orow[ px0     *18 + oc0] = acc[nt][0] + bias;
            orow[(px0 + 8)*18 + oc0] = acc[nt][2] + bias;
        }
        if (oc0 + 1 < 18) {
            float bias = __ldg(boff + oc0 + 1);
            orow[ px0     *18 + oc0 + 1] = acc[nt][1] + bias;
            orow[(px0 + 8)*18 + oc0 + 1] = acc[nt][3] + bias;
        }
    }
}

// ---------------- kernel 3: deformable conv, software-pipelined mma.sync tf32 ----------------
// grid (8,32): one (b,row-pair) per CTA, M=128 px, N=128 o, K=9*128.
// 512 thr = 16 warps (4m x 4n of 32x32 tiles), 1 CTA/SM.
// A double-buffered: tap k+1's gather LDGs are issued before/between the two
// GEMM halves of tap k (4 px held in regs, STS deferred) -> LDG latency hidden.
// W single-buffered via cp.async issued after the tap barrier.
#define ASZ 16896                       // 128*132 floats per A buffer
#define SMD_TOTAL ((2*16896 + 128*136 + 128*18)*4)

__global__ __launch_bounds__(512, 1) void k_deform_mma(const float* __restrict__ bdc,
                                                       float* __restrict__ out)
{
    extern __shared__ float smd[];
    float* As0  = smd;                       // 2 x 128*132
    float* Ws   = smd + 2*ASZ;               // 128*136
    float* offs = smd + 2*ASZ + 128*136;     // 128*18
    const int t = threadIdx.x, warp = t >> 5, lane = t & 31;
    const int r = lane >> 2, tig = lane & 3;
    const int b = blockIdx.x, y0 = blockIdx.y * 2;
    const int mbase = (warp & 3) * 32;
    const int nbase = (warp >> 2) * 32;
    const uint32_t ws_u32 = (uint32_t)__cvta_generic_to_shared(Ws);

    {
        const float* orow = g_off + ((size_t)b*64 + y0)*64*18;
        for (int i = t; i < 2304; i += 512) offs[i] = orow[i];
    }

    float acc[2][4][4];
    #pragma unroll
    for (int mt = 0; mt < 2; ++mt)
        #pragma unroll
        for (int nt = 0; nt < 4; ++nt)
            #pragma unroll
            for (int q = 0; q < 4; ++q) acc[mt][nt][q] = 0.f;

    const float* hb = g_h + (size_t)b*4096*128 + lane*4;

    // bilinear gather of one px for tap kk -> float4 (c = lane*4 .. lane*4+3)
    auto gather_px = [&](int kk, int px) -> float4 {
        const int ky = kk/3 - 1, kx = kk - (kk/3)*3 - 1;
        const int row = y0 + (px >> 6), xx = px & 63;
        const float dy = offs[px*18 + 2*kk];
        const float dx = offs[px*18 + 2*kk + 1];
        const float py  = (float)(row + ky) + dy;
        const float pxf = (float)(xx  + kx) + dx;
        const float fy = floorf(py), fx = floorf(pxf);
        const int yi = (int)fy, xi = (int)fx;
        const float wy = py - fy, wx = pxf - fx;
        const float w00 = (1.f-wy)*(1.f-wx), w01 = (1.f-wy)*wx;
        const float w10 = wy*(1.f-wx),       w11 = wy*wx;
        float4 rv = make_float4(0.f,0.f,0.f,0.f);
        if ((unsigned)yi < 64u) {
            const float* rp = hb + (size_t)yi*8192;
            if ((unsigned)xi     < 64u) { float4 c = *(const float4*)(rp + xi*128);
                rv.x += w00*c.x; rv.y += w00*c.y; rv.z += w00*c.z; rv.w += w00*c.w; }
            if ((unsigned)(xi+1) < 64u) { float4 c = *(const float4*)(rp + (xi+1)*128);
                rv.x += w01*c.x; rv.y += w01*c.y; rv.z += w01*c.z; rv.w += w01*c.w; }
        }
        if ((unsigned)(yi+1) < 64u) {
            const float* rp = hb + (size_t)(yi+1)*8192;
            if ((unsigned)xi     < 64u) { float4 c = *(const float4*)(rp + xi*128);
                rv.x += w10*c.x; rv.y += w10*c.y; rv.z += w10*c.z; rv.w += w10*c.w; }
            if ((unsigned)(xi+1) < 64u) { float4 c = *(const float4*)(rp + (xi+1)*128);
                rv.x += w11*c.x; rv.y += w11*c.y; rv.z += w11*c.z; rv.w += w11*c.w; }
        }
        rv.x = cvt_tf32(rv.x); rv.y = cvt_tf32(rv.y);
        rv.z = cvt_tf32(rv.z); rv.w = cvt_tf32(rv.w);
        return rv;
    };
    auto stage_w = [&](int kk){
        const float* src = g_wtf + kk*16384;
        #pragma unroll
        for (int j = 0; j < 8; ++j) {
            int i4 = j*512 + t;
            int o = i4 >> 5, c = (i4 & 31) * 4;
            cp_async16(ws_u32 + (uint32_t)(o*136 + c)*4u, src + i4*4);
        }
        CP_ASYNC_COMMIT();
    };

    // prologue: W0 async + full gather of tap 0 into As[0]
    stage_w(0);
    __syncthreads();   // offs staged before gather reads it
    #pragma unroll
    for (int pp = 0; pp < 8; ++pp) {
        const int px = pp*16 + warp;
        float4 rv = gather_px(0, px);
        *(float4*)(As0 + px*132 + lane*4) = rv;
    }
    CP_ASYNC_WAIT0();
    __syncthreads();

    for (int k = 0; k < 9; ++k) {
        const float* Ab = As0 + (k & 1)*ASZ;
        float* An = As0 + ((k + 1) & 1)*ASZ;
        const int kn = k + 1;
        float4 rv[4];
        // gather first 4 px of next tap (LDG latency hides under GEMM half 1)
        if (kn < 9) {
            #pragma unroll
            for (int pp = 0; pp < 4; ++pp) rv[pp] = gather_px(kn, pp*16 + warp);
        }
        // GEMM half 1: s = 0..7
        #pragma unroll
        for (int s = 0; s < 8; ++s) {
            uint32_t a[2][4];
            #pragma unroll
            for (int mt = 0; mt < 2; ++mt) {
                const float* ap = Ab + (mbase + mt*16 + r)*132 + s*8 + tig;
                a[mt][0] = __float_as_uint(ap[0]);
                a[mt][1] = __float_as_uint(ap[8*132]);
                a[mt][2] = __float_as_uint(ap[4]);
                a[mt][3] = __float_as_uint(ap[8*132 + 4]);
            }
            uint32_t bb[4][2];
            #pragma unroll
            for (int nt = 0; nt < 4; ++nt) {
                float2 bv = *(const float2*)(Ws + (nbase + nt*8 + r)*136 + s*8 + 2*tig);
                bb[nt][0] = __float_as_uint(bv.x);
                bb[nt][1] = __float_as_uint(bv.y);
            }
            #pragma unroll
            for (int mt = 0; mt < 2; ++mt)
                #pragma unroll
                for (int nt = 0; nt < 4; ++nt)
                    mma_tf32(acc[mt][nt][0], acc[mt][nt][1], acc[mt][nt][2], acc[mt][nt][3],
                             a[mt][0], a[mt][1], a[mt][2], a[mt][3], bb[nt][0], bb[nt][1]);
        }
        // deposit first half, gather second half
        if (kn < 9) {
            #pragma unroll
            for (int pp = 0; pp < 4; ++pp)
                *(float4*)(An + (pp*16 + warp)*132 + lane*4) = rv[pp];
            #pragma unroll
            for (int pp = 0; pp < 4; ++pp) rv[pp] = gather_px(kn, (pp + 4)*16 + warp);
        }
        // GEMM half 2: s = 8..15
        #pragma unroll
        for (int s = 8; s < 16; ++s) {
            uint32_t a[2][4];
            #pragma unroll
            for (int mt = 0; mt < 2; ++mt) {
                const float* ap = Ab + (mbase + mt*16 + r)*132 + s*8 + tig;
                a[mt][0] = __float_as_uint(ap[0]);
                a[mt][1] = __float_as_uint(ap[8*132]);
                a[mt][2] = __float_as_uint(ap[4]);
                a[mt][3] = __float_as_uint(ap[8*132 + 4]);
            }
            uint32_t bb[4][2];
            #pragma unroll
            for (int nt = 0; nt < 4; ++nt) {
                float2 bv = *(const float2*)(Ws + (nbase + nt*8 + r)*136 + s*8 + 2*tig);
                bb[nt][0] = __float_as_uint(bv.x);
                bb[nt][1] = __float_as_uint(bv.y);
            }
            #pragma unroll
            for (int mt = 0; mt < 2; ++mt)
                #pragma unroll
                for (int nt = 0; nt < 4; ++nt)
                    mma_tf32(acc[mt][nt][0], acc[mt][nt][1], acc[mt][nt][2], acc[mt][nt][3],
                             a[mt][0], a[mt][1], a[mt][2], a[mt][3], bb[nt][0], bb[nt][1]);
        }
        if (kn < 9) {
            #pragma unroll
            for (int pp = 0; pp < 4; ++pp)
                *(float4*)(An + ((pp + 4)*16 + warp)*132 + lane*4) = rv[pp];
        }
        __syncthreads();          // Ws reads + An writes complete
        if (kn < 9) {
            stage_w(kn);          // safe: all warps past GEMM k
            CP_ASYNC_WAIT0();
            __syncthreads();
        }
    }
    __syncthreads();
    // epilogue: acc -> smem [o][px] stride 132 (conflict-free both phases) -> NCHW
    float* epi = As0;
    #pragma unroll
    for (int mt = 0; mt < 2; ++mt)
        #pragma unroll
        for (int nt = 0; nt < 4; ++nt) {
            const int col0 = nbase + nt*8 + 2*tig;
            const int px0  = mbase + mt*16 + r;
            epi[ col0   *132 + px0    ] = acc[mt][nt][0];
            epi[(col0+1)*132 + px0    ] = acc[mt][nt][1];
            epi[ col0   *132 + px0 + 8] = acc[mt][nt][2];
            epi[(col0+1)*132 + px0 + 8] = acc[mt][nt][3];
        }
    __syncthreads();
    for (int i = t; i < 16384; i += 512) {
        const int o = i >> 7, px = i & 127;
        const int row = y0 + (px >> 6), xx = px & 63;
        out[(((size_t)b*128 + o)*64 + row)*64 + xx] = epi[o*132 + px] + __ldg(bdc + o);
    }
}

// ---------------- launch ----------------
extern "C" void kernel_launch(void* const* d_in, const int* in_sizes, int n_in,
                              void* d_out, int out_size)
{
    const float* x     = (const float*)d_in[0];
    const float* gam   = (const float*)d_in[1];
    const float* bet   = (const float*)d_in[2];
    const float* mea   = (const float*)d_in[3];
    const float* var   = (const float*)d_in[4];
    const float* woff  = (const float*)d_in[5];
    const float* boff  = (const float*)d_in[6];
    const float* wdc   = (const float*)d_in[7];
    const float* bdc   = (const float*)d_in[8];
    float* out = (float*)d_out;

    cudaFuncSetAttribute(k_off_mma,    cudaFuncAttributeMaxDynamicSharedMemorySize, SMO_TOTAL);
    cudaFuncSetAttribute(k_deform_mma, cudaFuncAttributeMaxDynamicSharedMemorySize, SMD_TOTAL);

    k_prep<<<(9*128*128 + 255)/256, 256>>>(woff, wdc);
    k_bnrelu<<<dim3(8,64), 256>>>(x, gam, bet, mea, var);
    k_off_mma<<<dim3(8,64), 256, SMO_TOTAL>>>(boff);
    k_deform_mma<<<dim3(8,32), 512, SMD_TOTAL>>>(bdc, out);
}